// round 3
// baseline (speedup 1.0000x reference)
#include <cuda_runtime.h>
#include <cstdint>
#include <cstddef>

#define Bn   128
#define Sn   256
#define GM   (Bn*Sn)         // 32768
#define NEGV (-10000.0f)

// ---------------- scratch (device globals; no allocation allowed) ----------------
__device__ float g_x [GM*130];            // concat(word_emb, char_feat)
__device__ float g_xw[2u*GM*400];         // x @ wih^T + (bih+bhh), per direction
__device__ float g_h [2u*GM*100];         // hidden states f/b
__device__ float g_em[GM*32];             // emissions

__device__ __forceinline__ float sigmf(float x){ return 1.0f/(1.0f+__expf(-x)); }
__device__ __forceinline__ float tanh_fast(float x){ return 1.0f - 2.0f/(__expf(2.0f*x)+1.0f); }

// ---------------- kernel 1: char CNN + embedding concat -> g_x ----------------
// Warp per (b,s) token; lane = filter (30 of 32 active). Only per-thread array
// is w[96] (own filter weights, statically indexed). Char window is in shared
// memory, zero-padded to 16 row slots, read as broadcast LDS.128.
__global__ __launch_bounds__(128) void k_embed_cnn(
    const float* __restrict__ word_emb, const float* __restrict__ char_emb,
    const float* __restrict__ conv_w,   const float* __restrict__ conv_b,
    const int*   __restrict__ word_x,   const int*   __restrict__ char_x)
{
    __shared__ float sw[96*32];        // [i=k*32+d][filter]  (d padded 30->32)
    __shared__ float srow[4][16][32];  // [local bs][row slot][d padded]

    int tid  = threadIdx.x;
    int lane = tid & 31;
    int wb   = tid >> 5;               // local token 0..3
    int bs0  = blockIdx.x * 4;
    int bs   = bs0 + wb;

    // stage weights transposed: sw[(k*32+d)*32 + f]
    for (int idx = tid; idx < 96*32; idx += 128){
        int i = idx >> 5, f = idx & 31;
        int k = i >> 5,  d = i & 31;
        sw[idx] = (f < 30 && d < 30) ? conv_w[f*90 + k*30 + d] : 0.0f;
    }
    // zero the row buffer
    for (int idx = tid; idx < 4*16*32; idx += 128)
        ((float*)srow)[idx] = 0.0f;
    __syncthreads();

    // fill rows 2..11 (slot = l+2) for the 4 tokens
    for (int idx = tid; idx < 4*10*30; idx += 128){
        int lb  = idx / 300;
        int rem = idx % 300;
        int l   = rem / 30;
        int d   = rem % 30;
        int c   = char_x[(bs0 + lb)*10 + l];
        srow[lb][l+2][d] = char_emb[c*30 + d];
    }
    __syncthreads();

    // each lane pulls its filter's weights into registers (static indexing)
    float w[96];
#pragma unroll
    for (int i = 0; i < 96; i++) w[i] = sw[i*32 + lane];

    float best = -1e30f;
#pragma unroll
    for (int p = 0; p < 12; p++){
        float acc = 0.0f;
#pragma unroll
        for (int k = 0; k < 3; k++){
#pragma unroll
            for (int q = 0; q < 8; q++){
                float4 ce = *(const float4*)&srow[wb][p + k][q*4];  // broadcast
                acc += w[k*32 + q*4 + 0]*ce.x;
                acc += w[k*32 + q*4 + 1]*ce.y;
                acc += w[k*32 + q*4 + 2]*ce.z;
                acc += w[k*32 + q*4 + 3]*ce.w;
            }
        }
        best = fmaxf(best, acc);
    }

    // write output row: word emb (cooperative) + char feature (per lane)
    int wid = word_x[bs];
    const float* wrow = word_emb + (size_t)wid*100;
    float* xo = g_x + (size_t)bs*130;
    for (int i = lane; i < 100; i += 32) xo[i] = wrow[i];
    if (lane < 30) xo[100 + lane] = best + conv_b[lane];
}

// ---------------- kernel 2: input-projection SGEMM -> g_xw ----------------
// C[m,n] = sum_k x[m,k] * W[n,k] + bias[n], n in [0,800): dir = n/400, j = n%400
__global__ __launch_bounds__(256) void k_gemm_in(
    const float* __restrict__ wih_f, const float* __restrict__ wih_b,
    const float* __restrict__ bih_f, const float* __restrict__ bhh_f,
    const float* __restrict__ bih_b, const float* __restrict__ bhh_b)
{
    __shared__ float As[65][68];
    __shared__ float Bs[65][68];
    int tid = threadIdx.x;
    int m0 = blockIdx.y*64;
    int n0 = blockIdx.x*64;
    int tx = tid & 15, ty = tid >> 4;

    float acc[4][4];
#pragma unroll
    for (int r=0;r<4;r++)
#pragma unroll
        for (int c=0;c<4;c++) acc[r][c] = 0.0f;

    for (int k0=0; k0<130; k0+=65){
        for (int idx=tid; idx<64*65; idx+=256){
            int ml = idx/65, k = idx%65;
            As[k][ml] = g_x[(size_t)(m0+ml)*130 + k0 + k];
        }
        for (int idx=tid; idx<64*65; idx+=256){
            int nl = idx/65, k = idx%65;
            int n  = n0+nl;
            float v = 0.0f;
            if (n < 800){
                const float* wp = (n<400) ? wih_f : wih_b;
                v = wp[(size_t)(n%400)*130 + k0 + k];
            }
            Bs[k][nl] = v;
        }
        __syncthreads();
#pragma unroll 5
        for (int k=0;k<65;k++){
            float4 a = *(const float4*)&As[k][ty*4];
            float4 b = *(const float4*)&Bs[k][tx*4];
            acc[0][0]+=a.x*b.x; acc[0][1]+=a.x*b.y; acc[0][2]+=a.x*b.z; acc[0][3]+=a.x*b.w;
            acc[1][0]+=a.y*b.x; acc[1][1]+=a.y*b.y; acc[1][2]+=a.y*b.z; acc[1][3]+=a.y*b.w;
            acc[2][0]+=a.z*b.x; acc[2][1]+=a.z*b.y; acc[2][2]+=a.z*b.z; acc[2][3]+=a.z*b.w;
            acc[3][0]+=a.w*b.x; acc[3][1]+=a.w*b.y; acc[3][2]+=a.w*b.z; acc[3][3]+=a.w*b.w;
        }
        __syncthreads();
    }

#pragma unroll
    for (int r=0;r<4;r++)
#pragma unroll
        for (int c=0;c<4;c++){
            int m = m0 + ty*4 + r;
            int n = n0 + tx*4 + c;
            if (n < 800){
                int dir = n/400, jj = n%400;
                float bias = dir ? (bih_b[jj]+bhh_b[jj]) : (bih_f[jj]+bhh_f[jj]);
                g_xw[(size_t)dir*GM*400 + (size_t)m*400 + jj] = acc[r][c] + bias;
            }
        }
}

// ---------------- kernel 3: persistent LSTM recurrence (both dirs) -> g_h ----------------
// 256 blocks: dir = bx>>7, one batch element per block. whh row j in registers.
__global__ __launch_bounds__(400,1) void k_lstm(
    const float* __restrict__ whh_f, const float* __restrict__ whh_b)
{
    int bx  = blockIdx.x;
    int dir = bx >> 7;
    int b   = bx & 127;
    int j   = threadIdx.x;          // 0..399 (gate-row)

    const float* whh = dir ? whh_b : whh_f;
    const float4* wrow = (const float4*)(whh + (size_t)j*100);
    float4 w[25];
#pragma unroll
    for (int q=0;q<25;q++) w[q] = wrow[q];

    __shared__ float h_s[100];
    __shared__ float gsh[400];
    if (j < 100) h_s[j] = 0.0f;
    float c_reg = 0.0f;

    const float* xw   = g_xw + (size_t)dir*GM*400 + (size_t)b*256*400;
    float*       hout = g_h  + (size_t)dir*GM*100 + (size_t)b*256*100;
    __syncthreads();

    for (int step=0; step<256; step++){
        int t = dir ? (255-step) : step;
        float a = xw[(size_t)t*400 + j];

        float s0 = 0.0f, s1 = 0.0f;
#pragma unroll
        for (int q=0;q<25;q++){
            float4 wq = w[q];
            float4 h4 = *(const float4*)&h_s[q*4];
            s0 += wq.x*h4.x + wq.y*h4.y;
            s1 += wq.z*h4.z + wq.w*h4.w;
        }
        gsh[j] = a + (s0 + s1);
        __syncthreads();

        if (j < 100){
            float gi = gsh[j];
            float gf = gsh[100+j];
            float gg = gsh[200+j];
            float go = gsh[300+j];
            float ct = sigmf(gf)*c_reg + sigmf(gi)*tanh_fast(gg);
            c_reg = ct;
            float h = sigmf(go)*tanh_fast(ct);
            h_s[j] = h;
            hout[(size_t)t*100 + j] = h;
        }
        __syncthreads();
    }
}

// ---------------- kernel 4: emission projection -> g_em ----------------
__global__ __launch_bounds__(256) void k_emis(
    const float* __restrict__ proj_w, const float* __restrict__ proj_b)
{
    __shared__ float pw[200*32];   // [k][tag]
    __shared__ float pb[32];
    int tid = threadIdx.x;
    for (int idx=tid; idx<6400; idx+=256){
        int tag = idx/200, k = idx%200;
        pw[k*32+tag] = proj_w[idx];
    }
    if (tid < 32) pb[tid] = proj_b[tid];
    __syncthreads();

    int tag = tid & 31, bsl = tid >> 5;
    int bs  = blockIdx.x*8 + bsl;          // grid 4096 * 8 = 32768
    const float* hf = g_h + (size_t)bs*100;
    const float* hb = g_h + (size_t)GM*100 + (size_t)bs*100;

    float acc = pb[tag];
#pragma unroll
    for (int q=0;q<25;q++){
        float4 h4 = *(const float4*)(hf + q*4);
        acc += h4.x*pw[(q*4+0)*32+tag];
        acc += h4.y*pw[(q*4+1)*32+tag];
        acc += h4.z*pw[(q*4+2)*32+tag];
        acc += h4.w*pw[(q*4+3)*32+tag];
    }
#pragma unroll
    for (int q=0;q<25;q++){
        float4 h4 = *(const float4*)(hb + q*4);
        acc += h4.x*pw[(100+q*4+0)*32+tag];
        acc += h4.y*pw[(100+q*4+1)*32+tag];
        acc += h4.z*pw[(100+q*4+2)*32+tag];
        acc += h4.w*pw[(100+q*4+3)*32+tag];
    }
    g_em[(size_t)bs*32 + tag] = acc;
}

// ---------------- kernel 5: CRF forward + gold score + loss ----------------
__global__ __launch_bounds__(32) void k_crf(
    const float* __restrict__ trans, const int* __restrict__ y, float* __restrict__ out)
{
    __shared__ float tr[32*33];
    __shared__ float la_s[32];
    int j = threadIdx.x, b = blockIdx.x;

    for (int idx=j; idx<1024; idx+=32)
        tr[(idx>>5)*33 + (idx&31)] = trans[idx];
    la_s[j] = (j==30) ? 0.0f : NEGV;

    float score = 0.0f;
    for (int t=j; t<256; t+=32){
        int cur  = y[b*256+t];
        int prev = (t==0) ? 30 : y[b*256+t-1];
        score += g_em[(size_t)(b*256+t)*32 + cur] + trans[prev*32+cur];
    }
    __syncwarp();

    for (int t=0; t<256; t++){
        float emv = g_em[(size_t)(b*256+t)*32 + j];
        float m = -1e30f;
#pragma unroll
        for (int i=0;i<32;i++) m = fmaxf(m, la_s[i] + tr[i*33+j]);
        float s = 0.0f;
#pragma unroll
        for (int i=0;i<32;i++) s += __expf((la_s[i] + tr[i*33+j]) - m);
        float nl = emv + m + __logf(s);
        __syncwarp();
        la_s[j] = nl;
        __syncwarp();
    }

    float la = la_s[j] + tr[j*33+31];                 // + trans[:, END]
    float m = la;
#pragma unroll
    for (int o=16;o>0;o>>=1) m = fmaxf(m, __shfl_xor_sync(0xffffffffu, m, o));
    float e = __expf(la - m);
#pragma unroll
    for (int o=16;o>0;o>>=1) e += __shfl_xor_sync(0xffffffffu, e, o);
    float total = m + __logf(e);

#pragma unroll
    for (int o=16;o>0;o>>=1) score += __shfl_xor_sync(0xffffffffu, score, o);

    if (j==0){
        score += trans[y[b*256+255]*32 + 31];          // trans[y_last, END]
        atomicAdd(out, (total - score) * (1.0f/128.0f));
    }
}

// ---------------- launch ----------------
extern "C" void kernel_launch(void* const* d_in, const int* in_sizes, int n_in,
                              void* d_out, int out_size)
{
    const float* word_emb = (const float*)d_in[0];
    const float* char_emb = (const float*)d_in[1];
    const float* conv_w   = (const float*)d_in[2];
    const float* conv_b   = (const float*)d_in[3];
    const float* wih_f    = (const float*)d_in[4];
    const float* whh_f    = (const float*)d_in[5];
    const float* bih_f    = (const float*)d_in[6];
    const float* bhh_f    = (const float*)d_in[7];
    const float* wih_b    = (const float*)d_in[8];
    const float* whh_b    = (const float*)d_in[9];
    const float* bih_b    = (const float*)d_in[10];
    const float* bhh_b    = (const float*)d_in[11];
    const float* proj_w   = (const float*)d_in[12];
    const float* proj_b   = (const float*)d_in[13];
    const float* trans    = (const float*)d_in[14];
    const int*   word_x   = (const int*)d_in[15];
    const int*   char_x   = (const int*)d_in[16];
    const int*   y        = (const int*)d_in[17];
    float* out = (float*)d_out;

    k_embed_cnn<<<8192,128>>>(word_emb, char_emb, conv_w, conv_b, word_x, char_x);
    dim3 gg(13, 512);
    k_gemm_in<<<gg,256>>>(wih_f, wih_b, bih_f, bhh_f, bih_b, bhh_b);
    k_lstm<<<256,400>>>(whh_f, whh_b);
    k_emis<<<4096,256>>>(proj_w, proj_b);
    cudaMemsetAsync(out, 0, sizeof(float));
    k_crf<<<128,32>>>(trans, y, out);
}

// round 4
// speedup vs baseline: 1.3473x; 1.3473x over previous
#include <cuda_runtime.h>
#include <cstdint>
#include <cstddef>

#define Bn   128
#define Sn   256
#define GM   (Bn*Sn)         // 32768
#define NEGV (-10000.0f)

typedef unsigned long long u64;

// ---------------- scratch (device globals; no allocation allowed) ----------------
__device__ float g_x [GM*130];            // concat(word_emb, char_feat)
__device__ float g_wt[130*800];           // transposed input weights [k][n]
__device__ float g_xw[2u*GM*400];         // x @ wih^T + (bih+bhh), per direction
__device__ float g_h [2u*GM*100];         // hidden states f/b
__device__ float g_em[GM*32];             // emissions

__device__ __forceinline__ float sigmf(float x){ return 1.0f/(1.0f+__expf(-x)); }
__device__ __forceinline__ float tanh_fast(float x){ return 1.0f - 2.0f/(__expf(2.0f*x)+1.0f); }

// packed f32x2 helpers (Blackwell; ptxas never auto-fuses these)
__device__ __forceinline__ void fma2(u64 &d, u64 a, u64 b){
    asm("fma.rn.f32x2 %0, %1, %2, %0;" : "+l"(d) : "l"(a), "l"(b));
}
__device__ __forceinline__ u64 pack2(float x, float y){
    u64 r; asm("mov.b64 %0, {%1, %2};" : "=l"(r) : "f"(x), "f"(y)); return r;
}
__device__ __forceinline__ float2 unpack2(u64 v){
    float2 r; asm("mov.b64 {%0, %1}, %2;" : "=f"(r.x), "=f"(r.y) : "l"(v)); return r;
}

// ---------------- kernel 1: char CNN + embedding concat -> g_x ----------------
__global__ __launch_bounds__(128) void k_embed_cnn(
    const float* __restrict__ word_emb, const float* __restrict__ char_emb,
    const float* __restrict__ conv_w,   const float* __restrict__ conv_b,
    const int*   __restrict__ word_x,   const int*   __restrict__ char_x)
{
    __shared__ float sw[96*32];        // [i=k*32+d][filter]  (d padded 30->32)
    __shared__ float srow[4][16][32];  // [local bs][row slot][d padded]

    int tid  = threadIdx.x;
    int lane = tid & 31;
    int wb   = tid >> 5;               // local token 0..3
    int bs0  = blockIdx.x * 4;
    int bs   = bs0 + wb;

    for (int idx = tid; idx < 96*32; idx += 128){
        int i = idx >> 5, f = idx & 31;
        int k = i >> 5,  d = i & 31;
        sw[idx] = (f < 30 && d < 30) ? conv_w[f*90 + k*30 + d] : 0.0f;
    }
    for (int idx = tid; idx < 4*16*32; idx += 128)
        ((float*)srow)[idx] = 0.0f;
    __syncthreads();

    for (int idx = tid; idx < 4*10*30; idx += 128){
        int lb  = idx / 300;
        int rem = idx % 300;
        int l   = rem / 30;
        int d   = rem % 30;
        int c   = char_x[(bs0 + lb)*10 + l];
        srow[lb][l+2][d] = char_emb[c*30 + d];
    }
    __syncthreads();

    float w[96];
#pragma unroll
    for (int i = 0; i < 96; i++) w[i] = sw[i*32 + lane];

    float best = -1e30f;
#pragma unroll
    for (int p = 0; p < 12; p++){
        float acc = 0.0f;
#pragma unroll
        for (int k = 0; k < 3; k++){
#pragma unroll
            for (int q = 0; q < 8; q++){
                float4 ce = *(const float4*)&srow[wb][p + k][q*4];  // broadcast
                acc += w[k*32 + q*4 + 0]*ce.x;
                acc += w[k*32 + q*4 + 1]*ce.y;
                acc += w[k*32 + q*4 + 2]*ce.z;
                acc += w[k*32 + q*4 + 3]*ce.w;
            }
        }
        best = fmaxf(best, acc);
    }

    int wid = word_x[bs];
    const float* wrow = word_emb + (size_t)wid*100;
    float* xo = g_x + (size_t)bs*130;
    for (int i = lane; i < 100; i += 32) xo[i] = wrow[i];
    if (lane < 30) xo[100 + lane] = best + conv_b[lane];
}

// ---------------- kernel 1b: pretranspose input weights -> g_wt[k][n] ----------------
__global__ __launch_bounds__(256) void k_wt(
    const float* __restrict__ wih_f, const float* __restrict__ wih_b)
{
    int idx = blockIdx.x*256 + threadIdx.x;       // 130*800 = 104000
    if (idx >= 130*800) return;
    int k = idx / 800, n = idx % 800;
    g_wt[idx] = (n < 400) ? wih_f[(size_t)n*130 + k] : wih_b[(size_t)(n-400)*130 + k];
}

// ---------------- kernel 2: input-projection SGEMM (f32x2) -> g_xw ----------------
// 128x64 tile, 256 threads, 8x4 micro (4 row-pairs x 4 cols) in packed f32x2.
__global__ __launch_bounds__(256) void k_gemm_in(
    const float* __restrict__ bih_f, const float* __restrict__ bhh_f,
    const float* __restrict__ bih_b, const float* __restrict__ bhh_b)
{
    __shared__ float2 As2[64*66];   // [row-pair mp][k]   rows (2mp, 2mp+1)
    __shared__ float  Bs [65*68];   // [k][n-local]

    int tid = threadIdx.x;
    int m0 = blockIdx.y*128;
    int n0 = blockIdx.x*64;
    int tx = tid & 15, ty = tid >> 4;

    u64 acc[4][4];
#pragma unroll
    for (int r=0;r<4;r++)
#pragma unroll
        for (int c=0;c<4;c++) acc[r][c] = 0ull;

    for (int k0=0; k0<130; k0+=65){
        for (int idx=tid; idx<64*65; idx+=256){
            int mp = idx/65, k = idx%65;
            float lo = g_x[(size_t)(m0+2*mp  )*130 + k0 + k];
            float hi = g_x[(size_t)(m0+2*mp+1)*130 + k0 + k];
            As2[mp*66 + k] = make_float2(lo, hi);
        }
        for (int idx=tid; idx<65*64; idx+=256){
            int k = idx/64, nl = idx%64;
            int n = n0+nl;
            Bs[k*68 + nl] = (n < 800) ? g_wt[(size_t)(k0+k)*800 + n] : 0.0f;
        }
        __syncthreads();
#pragma unroll 5
        for (int k=0;k<65;k++){
            u64 a2[4];
#pragma unroll
            for (int r=0;r<4;r++)
                a2[r] = *(const u64*)&As2[(ty*4+r)*66 + k];
            float4 b4 = *(const float4*)&Bs[k*68 + tx*4];
            u64 b0 = pack2(b4.x, b4.x);
            u64 b1 = pack2(b4.y, b4.y);
            u64 b2 = pack2(b4.z, b4.z);
            u64 b3 = pack2(b4.w, b4.w);
#pragma unroll
            for (int r=0;r<4;r++){
                fma2(acc[r][0], a2[r], b0);
                fma2(acc[r][1], a2[r], b1);
                fma2(acc[r][2], a2[r], b2);
                fma2(acc[r][3], a2[r], b3);
            }
        }
        __syncthreads();
    }

#pragma unroll
    for (int r=0;r<4;r++)
#pragma unroll
        for (int c=0;c<4;c++){
            int n = n0 + tx*4 + c;
            if (n < 800){
                int dir = n/400, jj = n%400;
                float bias = dir ? (bih_b[jj]+bhh_b[jj]) : (bih_f[jj]+bhh_f[jj]);
                float2 v = unpack2(acc[r][c]);
                int m = m0 + ty*8 + 2*r;
                float* dst = g_xw + (size_t)dir*GM*400 + (size_t)m*400 + jj;
                dst[0]   = v.x + bias;
                dst[400] = v.y + bias;
            }
        }
}

// ---------------- kernel 3: persistent LSTM recurrence (f32x2) -> g_h ----------------
// 128 blocks: dir = bx>>6, two batch elems per block (w reused). f32x2 matvec.
__global__ __launch_bounds__(400,1) void k_lstm(
    const float* __restrict__ whh_f, const float* __restrict__ whh_b)
{
    int bx  = blockIdx.x;
    int dir = bx >> 6;
    int pr  = bx & 63;
    int b0  = pr*2, b1 = b0+1;
    int j   = threadIdx.x;          // 0..399 (gate-row)

    const float* whh = dir ? whh_b : whh_f;
    const ulonglong2* wrow = (const ulonglong2*)(whh + (size_t)j*100);
    ulonglong2 w[25];               // 50 packed k-pairs
#pragma unroll
    for (int q=0;q<25;q++) w[q] = wrow[q];

    __shared__ float h_s[2][104];   // 16B-aligned rows
    __shared__ float gsh[2][400];
    if (j < 200) h_s[j/100][j%100] = 0.0f;
    float c_reg = 0.0f;

    const float* xw   = g_xw + (size_t)dir*GM*400;
    float*       hout = g_h  + (size_t)dir*GM*100;
    __syncthreads();

    for (int step=0; step<256; step++){
        int t = dir ? (255-step) : step;
        float a0 = xw[(size_t)(b0*256+t)*400 + j];
        float a1 = xw[(size_t)(b1*256+t)*400 + j];

        u64 s0 = 0ull, s0b = 0ull, s1 = 0ull, s1b = 0ull;
#pragma unroll
        for (int q=0;q<25;q++){
            ulonglong2 wq = w[q];
            ulonglong2 h0 = *(const ulonglong2*)&h_s[0][q*4];
            ulonglong2 h1 = *(const ulonglong2*)&h_s[1][q*4];
            fma2(s0,  wq.x, h0.x);
            fma2(s0b, wq.y, h0.y);
            fma2(s1,  wq.x, h1.x);
            fma2(s1b, wq.y, h1.y);
        }
        float2 r0 = unpack2(s0), r0b = unpack2(s0b);
        float2 r1 = unpack2(s1), r1b = unpack2(s1b);
        gsh[0][j] = a0 + ((r0.x+r0.y)+(r0b.x+r0b.y));
        gsh[1][j] = a1 + ((r1.x+r1.y)+(r1b.x+r1b.y));
        __syncthreads();

        if (j < 200){
            int bb = (j >= 100), k = j - bb*100;
            float gi = gsh[bb][k];
            float gf = gsh[bb][100+k];
            float gg = gsh[bb][200+k];
            float go = gsh[bb][300+k];
            float ct = sigmf(gf)*c_reg + sigmf(gi)*tanh_fast(gg);
            c_reg = ct;
            float h = sigmf(go)*tanh_fast(ct);
            h_s[bb][k] = h;
            hout[(size_t)((bb?b1:b0)*256+t)*100 + k] = h;
        }
        __syncthreads();
    }
}

// ---------------- kernel 4: emission projection (tiled) -> g_em ----------------
// Block = 64 bs rows; hs tile + pw in smem; thread computes 8 outputs.
__global__ __launch_bounds__(256) void k_emis(
    const float* __restrict__ proj_w, const float* __restrict__ proj_b)
{
    __shared__ float hs[64*204];   // [m][k] padded row stride
    __shared__ float pw[200*32];   // [k][tag]
    __shared__ float pb[32];

    int tid = threadIdx.x;
    int bs0 = blockIdx.x*64;

    for (int idx=tid; idx<6400; idx+=256){
        int tag = idx/200, k = idx%200;
        pw[k*32+tag] = proj_w[idx];
    }
    if (tid < 32) pb[tid] = proj_b[tid];

    for (int idx=tid; idx<64*50; idx+=256){
        int m = idx/50, q = idx%50;
        int bs = bs0 + m;
        const float* src = (q < 25) ? (g_h + (size_t)bs*100 + q*4)
                                    : (g_h + (size_t)GM*100 + (size_t)bs*100 + (q-25)*4);
        float4 v = *(const float4*)src;
        *(float4*)&hs[m*204 + q*4] = v;
    }
    __syncthreads();

    int tag  = tid & 31;
    int msub = tid >> 5;           // 0..7

    float acc[8];
#pragma unroll
    for (int i=0;i<8;i++) acc[i] = pb[tag];

    for (int k=0;k<200;k++){
        float pwv = pw[k*32 + tag];
#pragma unroll
        for (int i=0;i<8;i++)
            acc[i] += hs[(msub + 8*i)*204 + k] * pwv;   // broadcast read
    }
#pragma unroll
    for (int i=0;i<8;i++)
        g_em[(size_t)(bs0 + msub + 8*i)*32 + tag] = acc[i];
}

// ---------------- kernel 5: CRF forward + gold score + loss ----------------
__global__ __launch_bounds__(32) void k_crf(
    const float* __restrict__ trans, const int* __restrict__ y, float* __restrict__ out)
{
    __shared__ float tr[32*33];
    __shared__ float la_s[32];
    int j = threadIdx.x, b = blockIdx.x;

    for (int idx=j; idx<1024; idx+=32)
        tr[(idx>>5)*33 + (idx&31)] = trans[idx];
    la_s[j] = (j==30) ? 0.0f : NEGV;

    float score = 0.0f;
    for (int t=j; t<256; t+=32){
        int cur  = y[b*256+t];
        int prev = (t==0) ? 30 : y[b*256+t-1];
        score += g_em[(size_t)(b*256+t)*32 + cur] + trans[prev*32+cur];
    }
    __syncwarp();

    for (int t=0; t<256; t++){
        float emv = g_em[(size_t)(b*256+t)*32 + j];
        float m = -1e30f;
#pragma unroll
        for (int i=0;i<32;i++) m = fmaxf(m, la_s[i] + tr[i*33+j]);
        float s = 0.0f;
#pragma unroll
        for (int i=0;i<32;i++) s += __expf((la_s[i] + tr[i*33+j]) - m);
        float nl = emv + m + __logf(s);
        __syncwarp();
        la_s[j] = nl;
        __syncwarp();
    }

    float la = la_s[j] + tr[j*33+31];
    float m = la;
#pragma unroll
    for (int o=16;o>0;o>>=1) m = fmaxf(m, __shfl_xor_sync(0xffffffffu, m, o));
    float e = __expf(la - m);
#pragma unroll
    for (int o=16;o>0;o>>=1) e += __shfl_xor_sync(0xffffffffu, e, o);
    float total = m + __logf(e);

#pragma unroll
    for (int o=16;o>0;o>>=1) score += __shfl_xor_sync(0xffffffffu, score, o);

    if (j==0){
        score += trans[y[b*256+255]*32 + 31];
        atomicAdd(out, (total - score) * (1.0f/128.0f));
    }
}

// ---------------- launch ----------------
extern "C" void kernel_launch(void* const* d_in, const int* in_sizes, int n_in,
                              void* d_out, int out_size)
{
    const float* word_emb = (const float*)d_in[0];
    const float* char_emb = (const float*)d_in[1];
    const float* conv_w   = (const float*)d_in[2];
    const float* conv_b   = (const float*)d_in[3];
    const float* wih_f    = (const float*)d_in[4];
    const float* whh_f    = (const float*)d_in[5];
    const float* bih_f    = (const float*)d_in[6];
    const float* bhh_f    = (const float*)d_in[7];
    const float* wih_b    = (const float*)d_in[8];
    const float* whh_b    = (const float*)d_in[9];
    const float* bih_b    = (const float*)d_in[10];
    const float* bhh_b    = (const float*)d_in[11];
    const float* proj_w   = (const float*)d_in[12];
    const float* proj_b   = (const float*)d_in[13];
    const float* trans    = (const float*)d_in[14];
    const int*   word_x   = (const int*)d_in[15];
    const int*   char_x   = (const int*)d_in[16];
    const int*   y        = (const int*)d_in[17];
    float* out = (float*)d_out;

    k_embed_cnn<<<8192,128>>>(word_emb, char_emb, conv_w, conv_b, word_x, char_x);
    k_wt<<<(130*800+255)/256,256>>>(wih_f, wih_b);
    dim3 gg(13, 256);
    k_gemm_in<<<gg,256>>>(bih_f, bhh_f, bih_b, bhh_b);
    k_lstm<<<128,400>>>(whh_f, whh_b);
    k_emis<<<512,256>>>(proj_w, proj_b);
    cudaMemsetAsync(out, 0, sizeof(float));
    k_crf<<<128,32>>>(trans, y, out);
}

// round 5
// speedup vs baseline: 1.5067x; 1.1183x over previous
#include <cuda_runtime.h>
#include <cstdint>
#include <cstddef>

#define Bn   128
#define Sn   256
#define GM   (Bn*Sn)         // 32768
#define NEGV (-10000.0f)

typedef unsigned long long u64;

// ---------------- scratch (device globals; no allocation allowed) ----------------
__device__ float g_x [GM*130];            // concat(word_emb, char_feat)
__device__ float g_wt[130*800];           // transposed input weights [k][n]
__device__ float g_xw[2u*GM*400];         // x @ wih^T + (bih+bhh), per direction
__device__ float g_h [2u*GM*100];         // hidden states f/b
__device__ float g_em[GM*32];             // emissions

__device__ __forceinline__ float sigmf(float x){ return 1.0f/(1.0f+__expf(-x)); }
__device__ __forceinline__ float tanh_fast(float x){ return 1.0f - 2.0f/(__expf(2.0f*x)+1.0f); }

// packed f32x2 helpers (Blackwell; ptxas never auto-fuses these)
__device__ __forceinline__ void fma2(u64 &d, u64 a, u64 b){
    asm("fma.rn.f32x2 %0, %1, %2, %0;" : "+l"(d) : "l"(a), "l"(b));
}
__device__ __forceinline__ u64 pack2(float x, float y){
    u64 r; asm("mov.b64 %0, {%1, %2};" : "=l"(r) : "f"(x), "f"(y)); return r;
}
__device__ __forceinline__ float2 unpack2(u64 v){
    float2 r; asm("mov.b64 {%0, %1}, %2;" : "=f"(r.x), "=f"(r.y) : "l"(v)); return r;
}

// ---------------- kernel 1: char CNN + embedding concat -> g_x ----------------
__global__ __launch_bounds__(128) void k_embed_cnn(
    const float* __restrict__ word_emb, const float* __restrict__ char_emb,
    const float* __restrict__ conv_w,   const float* __restrict__ conv_b,
    const int*   __restrict__ word_x,   const int*   __restrict__ char_x)
{
    __shared__ float sw[96*32];        // [i=k*32+d][filter]  (d padded 30->32)
    __shared__ float srow[4][16][32];  // [local bs][row slot][d padded]

    int tid  = threadIdx.x;
    int lane = tid & 31;
    int wb   = tid >> 5;               // local token 0..3
    int bs0  = blockIdx.x * 4;
    int bs   = bs0 + wb;

    for (int idx = tid; idx < 96*32; idx += 128){
        int i = idx >> 5, f = idx & 31;
        int k = i >> 5,  d = i & 31;
        sw[idx] = (f < 30 && d < 30) ? conv_w[f*90 + k*30 + d] : 0.0f;
    }
    for (int idx = tid; idx < 4*16*32; idx += 128)
        ((float*)srow)[idx] = 0.0f;
    __syncthreads();

    for (int idx = tid; idx < 4*10*30; idx += 128){
        int lb  = idx / 300;
        int rem = idx % 300;
        int l   = rem / 30;
        int d   = rem % 30;
        int c   = char_x[(bs0 + lb)*10 + l];
        srow[lb][l+2][d] = char_emb[c*30 + d];
    }
    __syncthreads();

    float w[96];
#pragma unroll
    for (int i = 0; i < 96; i++) w[i] = sw[i*32 + lane];

    float best = -1e30f;
#pragma unroll
    for (int p = 0; p < 12; p++){
        float acc = 0.0f;
#pragma unroll
        for (int k = 0; k < 3; k++){
#pragma unroll
            for (int q = 0; q < 8; q++){
                float4 ce = *(const float4*)&srow[wb][p + k][q*4];  // broadcast
                acc += w[k*32 + q*4 + 0]*ce.x;
                acc += w[k*32 + q*4 + 1]*ce.y;
                acc += w[k*32 + q*4 + 2]*ce.z;
                acc += w[k*32 + q*4 + 3]*ce.w;
            }
        }
        best = fmaxf(best, acc);
    }

    int wid = word_x[bs];
    const float* wrow = word_emb + (size_t)wid*100;
    float* xo = g_x + (size_t)bs*130;
    for (int i = lane; i < 100; i += 32) xo[i] = wrow[i];
    if (lane < 30) xo[100 + lane] = best + conv_b[lane];
}

// ---------------- kernel 1b: pretranspose input weights -> g_wt[k][n] ----------------
__global__ __launch_bounds__(256) void k_wt(
    const float* __restrict__ wih_f, const float* __restrict__ wih_b)
{
    int idx = blockIdx.x*256 + threadIdx.x;       // 130*800 = 104000
    if (idx >= 130*800) return;
    int k = idx / 800, n = idx % 800;
    g_wt[idx] = (n < 400) ? wih_f[(size_t)n*130 + k] : wih_b[(size_t)(n-400)*130 + k];
}

// ---------------- kernel 2: input-projection SGEMM (f32x2) -> g_xw ----------------
__global__ __launch_bounds__(256) void k_gemm_in(
    const float* __restrict__ bih_f, const float* __restrict__ bhh_f,
    const float* __restrict__ bih_b, const float* __restrict__ bhh_b)
{
    __shared__ float2 As2[64*66];   // [row-pair mp][k]   rows (2mp, 2mp+1)
    __shared__ float  Bs [65*68];   // [k][n-local]

    int tid = threadIdx.x;
    int m0 = blockIdx.y*128;
    int n0 = blockIdx.x*64;
    int tx = tid & 15, ty = tid >> 4;

    u64 acc[4][4];
#pragma unroll
    for (int r=0;r<4;r++)
#pragma unroll
        for (int c=0;c<4;c++) acc[r][c] = 0ull;

    for (int k0=0; k0<130; k0+=65){
        for (int idx=tid; idx<64*65; idx+=256){
            int mp = idx/65, k = idx%65;
            float lo = g_x[(size_t)(m0+2*mp  )*130 + k0 + k];
            float hi = g_x[(size_t)(m0+2*mp+1)*130 + k0 + k];
            As2[mp*66 + k] = make_float2(lo, hi);
        }
        for (int idx=tid; idx<65*64; idx+=256){
            int k = idx/64, nl = idx%64;
            int n = n0+nl;
            Bs[k*68 + nl] = (n < 800) ? g_wt[(size_t)(k0+k)*800 + n] : 0.0f;
        }
        __syncthreads();
#pragma unroll 5
        for (int k=0;k<65;k++){
            u64 a2[4];
#pragma unroll
            for (int r=0;r<4;r++)
                a2[r] = *(const u64*)&As2[(ty*4+r)*66 + k];
            float4 b4 = *(const float4*)&Bs[k*68 + tx*4];
            u64 b0 = pack2(b4.x, b4.x);
            u64 b1 = pack2(b4.y, b4.y);
            u64 b2 = pack2(b4.z, b4.z);
            u64 b3 = pack2(b4.w, b4.w);
#pragma unroll
            for (int r=0;r<4;r++){
                fma2(acc[r][0], a2[r], b0);
                fma2(acc[r][1], a2[r], b1);
                fma2(acc[r][2], a2[r], b2);
                fma2(acc[r][3], a2[r], b3);
            }
        }
        __syncthreads();
    }

#pragma unroll
    for (int r=0;r<4;r++)
#pragma unroll
        for (int c=0;c<4;c++){
            int n = n0 + tx*4 + c;
            if (n < 800){
                int dir = n/400, jj = n%400;
                float bias = dir ? (bih_b[jj]+bhh_b[jj]) : (bih_f[jj]+bhh_f[jj]);
                float2 v = unpack2(acc[r][c]);
                int m = m0 + ty*8 + 2*r;
                float* dst = g_xw + (size_t)dir*GM*400 + (size_t)m*400 + jj;
                dst[0]   = v.x + bias;
                dst[400] = v.y + bias;
            }
        }
}

// ---------------- kernel 3: LSTM recurrence, K-split (800 thr) -> g_h ----------------
// 128 blocks: dir = bx>>6, two batch elems per block.
// thread = (gate j, k-half). Each thread holds HALF the whh row (<=52 regs),
// computes partial dot for both batch elems; partials combined in activation.
__global__ __launch_bounds__(800,1) void k_lstm(
    const float* __restrict__ whh_f, const float* __restrict__ whh_b)
{
    int bx  = blockIdx.x;
    int dir = bx >> 6;
    int pr  = bx & 63;
    int b0  = pr*2, b1 = b0+1;
    int tid = threadIdx.x;
    int half = (tid >= 400);
    int j    = half ? tid - 400 : tid;   // gate row 0..399
    int q0   = half ? 13 : 0;            // float4-group offset into h
    int nq   = half ? 12 : 13;

    const float* whh = dir ? whh_b : whh_f;
    const ulonglong2* wrow = (const ulonglong2*)(whh + (size_t)j*100);
    ulonglong2 w[13];
#pragma unroll
    for (int q=0;q<13;q++){
        if (q < nq) w[q] = wrow[q0+q];
        else { w[q].x = 0ull; w[q].y = 0ull; }
    }

    __shared__ float h_s[2][112];     // zero-padded; group 25 reads land in zeros
    __shared__ float sp[2][2][400];   // [half][batch][gate]
    if (tid < 224) ((float*)h_s)[tid] = 0.0f;
    float c_reg = 0.0f;

    const float* xw   = g_xw + (size_t)dir*GM*400;
    float*       hout = g_h  + (size_t)dir*GM*100;
    __syncthreads();

    for (int step=0; step<256; step++){
        int t = dir ? (255-step) : step;
        float a0 = 0.0f, a1 = 0.0f;
        if (!half){
            a0 = xw[(size_t)(b0*256+t)*400 + j];
            a1 = xw[(size_t)(b1*256+t)*400 + j];
        }

        u64 s0=0ull, s0b=0ull, s1=0ull, s1b=0ull;
#pragma unroll
        for (int q=0;q<13;q++){
            ulonglong2 wq = w[q];
            ulonglong2 h0 = *(const ulonglong2*)&h_s[0][(q0+q)*4];
            ulonglong2 h1 = *(const ulonglong2*)&h_s[1][(q0+q)*4];
            fma2(s0,  wq.x, h0.x);
            fma2(s0b, wq.y, h0.y);
            fma2(s1,  wq.x, h1.x);
            fma2(s1b, wq.y, h1.y);
        }
        float2 u0 = unpack2(s0), u0b = unpack2(s0b);
        float2 u1 = unpack2(s1), u1b = unpack2(s1b);
        sp[half][0][j] = a0 + ((u0.x+u0.y)+(u0b.x+u0b.y));
        sp[half][1][j] = a1 + ((u1.x+u1.y)+(u1b.x+u1b.y));
        __syncthreads();

        if (tid < 200){
            int bb = (tid >= 100), k = tid - bb*100;
            float gi = sp[0][bb][k]     + sp[1][bb][k];
            float gf = sp[0][bb][100+k] + sp[1][bb][100+k];
            float gg = sp[0][bb][200+k] + sp[1][bb][200+k];
            float go = sp[0][bb][300+k] + sp[1][bb][300+k];
            float ct = sigmf(gf)*c_reg + sigmf(gi)*tanh_fast(gg);
            c_reg = ct;
            float h = sigmf(go)*tanh_fast(ct);
            h_s[bb][k] = h;
            hout[(size_t)((bb?b1:b0)*256+t)*100 + k] = h;
        }
        __syncthreads();
    }
}

// ---------------- kernel 4: emission projection (tiled) -> g_em ----------------
__global__ __launch_bounds__(256) void k_emis(
    const float* __restrict__ proj_w, const float* __restrict__ proj_b)
{
    __shared__ float hs[64*204];   // [m][k] padded row stride
    __shared__ float pw[200*32];   // [k][tag]
    __shared__ float pb[32];

    int tid = threadIdx.x;
    int bs0 = blockIdx.x*64;

    for (int idx=tid; idx<6400; idx+=256){
        int tag = idx/200, k = idx%200;
        pw[k*32+tag] = proj_w[idx];
    }
    if (tid < 32) pb[tid] = proj_b[tid];

    for (int idx=tid; idx<64*50; idx+=256){
        int m = idx/50, q = idx%50;
        int bs = bs0 + m;
        const float* src = (q < 25) ? (g_h + (size_t)bs*100 + q*4)
                                    : (g_h + (size_t)GM*100 + (size_t)bs*100 + (q-25)*4);
        float4 v = *(const float4*)src;
        *(float4*)&hs[m*204 + q*4] = v;
    }
    __syncthreads();

    int tag  = tid & 31;
    int msub = tid >> 5;           // 0..7

    float acc[8];
#pragma unroll
    for (int i=0;i<8;i++) acc[i] = pb[tag];

    for (int k=0;k<200;k++){
        float pwv = pw[k*32 + tag];
#pragma unroll
        for (int i=0;i<8;i++)
            acc[i] += hs[(msub + 8*i)*204 + k] * pwv;   // broadcast read
    }
#pragma unroll
    for (int i=0;i<8;i++)
        g_em[(size_t)(bs0 + msub + 8*i)*32 + tag] = acc[i];
}

// ---------------- kernel 5: CRF (exp-factorized transitions) ----------------
// logsumexp_i(la_i + tr_ij + em_j) = em_j + m + log(sum_i e^{la_i-m} * T_ij),
// T_ij = e^{tr_ij} hoisted out of the time loop (1 EX2/step instead of 32).
__global__ __launch_bounds__(32) void k_crf(
    const float* __restrict__ trans, const int* __restrict__ y, float* __restrict__ out)
{
    __shared__ float E_s[32];
    int j = threadIdx.x, b = blockIdx.x;

    float T[32];
#pragma unroll
    for (int i=0;i<32;i++) T[i] = __expf(trans[i*32 + j]);   // exp(NEG)=0, safe
    float tend = trans[j*32 + 31];                           // trans[j, END]

    float la = (j==30) ? 0.0f : NEGV;

    float score = 0.0f;
    for (int t=j; t<256; t+=32){
        int cur  = y[b*256+t];
        int prev = (t==0) ? 30 : y[b*256+t-1];
        score += g_em[(size_t)(b*256+t)*32 + cur] + trans[prev*32+cur];
    }
    __syncwarp();

    float emv = g_em[(size_t)(b*256)*32 + j];
    for (int t=0; t<256; t++){
        float em_next = (t < 255) ? g_em[(size_t)(b*256+t+1)*32 + j] : 0.0f;

        float m = la;
#pragma unroll
        for (int o=16;o>0;o>>=1) m = fmaxf(m, __shfl_xor_sync(0xffffffffu, m, o));
        E_s[j] = __expf(la - m);
        __syncwarp();
        float s = 0.0f;
#pragma unroll
        for (int i=0;i<32;i++) s += E_s[i]*T[i];
        la = emv + m + __logf(s);
        __syncwarp();
        emv = em_next;
    }

    la += tend;
    float m = la;
#pragma unroll
    for (int o=16;o>0;o>>=1) m = fmaxf(m, __shfl_xor_sync(0xffffffffu, m, o));
    float e = __expf(la - m);
#pragma unroll
    for (int o=16;o>0;o>>=1) e += __shfl_xor_sync(0xffffffffu, e, o);
    float total = m + __logf(e);

#pragma unroll
    for (int o=16;o>0;o>>=1) score += __shfl_xor_sync(0xffffffffu, score, o);

    if (j==0){
        score += trans[y[b*256+255]*32 + 31];
        atomicAdd(out, (total - score) * (1.0f/128.0f));
    }
}

// ---------------- launch ----------------
extern "C" void kernel_launch(void* const* d_in, const int* in_sizes, int n_in,
                              void* d_out, int out_size)
{
    const float* word_emb = (const float*)d_in[0];
    const float* char_emb = (const float*)d_in[1];
    const float* conv_w   = (const float*)d_in[2];
    const float* conv_b   = (const float*)d_in[3];
    const float* wih_f    = (const float*)d_in[4];
    const float* whh_f    = (const float*)d_in[5];
    const float* bih_f    = (const float*)d_in[6];
    const float* bhh_f    = (const float*)d_in[7];
    const float* wih_b    = (const float*)d_in[8];
    const float* whh_b    = (const float*)d_in[9];
    const float* bih_b    = (const float*)d_in[10];
    const float* bhh_b    = (const float*)d_in[11];
    const float* proj_w   = (const float*)d_in[12];
    const float* proj_b   = (const float*)d_in[13];
    const float* trans    = (const float*)d_in[14];
    const int*   word_x   = (const int*)d_in[15];
    const int*   char_x   = (const int*)d_in[16];
    const int*   y        = (const int*)d_in[17];
    float* out = (float*)d_out;

    k_embed_cnn<<<8192,128>>>(word_emb, char_emb, conv_w, conv_b, word_x, char_x);
    k_wt<<<(130*800+255)/256,256>>>(wih_f, wih_b);
    dim3 gg(13, 256);
    k_gemm_in<<<gg,256>>>(bih_f, bhh_f, bih_b, bhh_b);
    k_lstm<<<128,800>>>(whh_f, whh_b);
    k_emis<<<512,256>>>(proj_w, proj_b);
    cudaMemsetAsync(out, 0, sizeof(float));
    k_crf<<<128,32>>>(trans, y, out);
}

// round 6
// speedup vs baseline: 1.5818x; 1.0499x over previous
#include <cuda_runtime.h>
#include <cstdint>
#include <cstddef>

#define Bn   128
#define Sn   256
#define GM   (Bn*Sn)         // 32768
#define NEGV (-10000.0f)

typedef unsigned long long u64;

// ---------------- scratch (device globals; no allocation allowed) ----------------
__device__ float g_x [GM*130];            // concat(word_emb, char_feat)
__device__ float g_wt[130*800];           // transposed input weights [k][n]
__device__ float g_xw[2u*GM*400];         // x @ wih^T + (bih+bhh), per direction
__device__ float g_h [2u*GM*100];         // hidden states f/b
__device__ float g_em[GM*32];             // emissions

__device__ __forceinline__ float mtanh(float x){
    float r; asm("tanh.approx.f32 %0, %1;" : "=f"(r) : "f"(x)); return r;
}
__device__ __forceinline__ float msigm(float x){ return fmaf(mtanh(0.5f*x), 0.5f, 0.5f); }

// packed f32x2 helpers (Blackwell; ptxas never auto-fuses these)
__device__ __forceinline__ void fma2(u64 &d, u64 a, u64 b){
    asm("fma.rn.f32x2 %0, %1, %2, %0;" : "+l"(d) : "l"(a), "l"(b));
}
__device__ __forceinline__ u64 pack2(float x, float y){
    u64 r; asm("mov.b64 %0, {%1, %2};" : "=l"(r) : "f"(x), "f"(y)); return r;
}
__device__ __forceinline__ float2 unpack2(u64 v){
    float2 r; asm("mov.b64 {%0, %1}, %2;" : "=f"(r.x), "=f"(r.y) : "l"(v)); return r;
}

// ---------------- kernel 1: char CNN + embedding concat -> g_x ----------------
__global__ __launch_bounds__(128) void k_embed_cnn(
    const float* __restrict__ word_emb, const float* __restrict__ char_emb,
    const float* __restrict__ conv_w,   const float* __restrict__ conv_b,
    const int*   __restrict__ word_x,   const int*   __restrict__ char_x)
{
    __shared__ float sw[96*32];        // [i=k*32+d][filter]  (d padded 30->32)
    __shared__ float srow[4][16][32];  // [local bs][row slot][d padded]

    int tid  = threadIdx.x;
    int lane = tid & 31;
    int wb   = tid >> 5;               // local token 0..3
    int bs0  = blockIdx.x * 4;
    int bs   = bs0 + wb;

    for (int idx = tid; idx < 96*32; idx += 128){
        int i = idx >> 5, f = idx & 31;
        int k = i >> 5,  d = i & 31;
        sw[idx] = (f < 30 && d < 30) ? conv_w[f*90 + k*30 + d] : 0.0f;
    }
    for (int idx = tid; idx < 4*16*32; idx += 128)
        ((float*)srow)[idx] = 0.0f;
    __syncthreads();

    for (int idx = tid; idx < 4*10*30; idx += 128){
        int lb  = idx / 300;
        int rem = idx % 300;
        int l   = rem / 30;
        int d   = rem % 30;
        int c   = char_x[(bs0 + lb)*10 + l];
        srow[lb][l+2][d] = char_emb[c*30 + d];
    }
    __syncthreads();

    float w[96];
#pragma unroll
    for (int i = 0; i < 96; i++) w[i] = sw[i*32 + lane];

    float best = -1e30f;
#pragma unroll
    for (int p = 0; p < 12; p++){
        float acc = 0.0f;
#pragma unroll
        for (int k = 0; k < 3; k++){
#pragma unroll
            for (int q = 0; q < 8; q++){
                float4 ce = *(const float4*)&srow[wb][p + k][q*4];  // broadcast
                acc += w[k*32 + q*4 + 0]*ce.x;
                acc += w[k*32 + q*4 + 1]*ce.y;
                acc += w[k*32 + q*4 + 2]*ce.z;
                acc += w[k*32 + q*4 + 3]*ce.w;
            }
        }
        best = fmaxf(best, acc);
    }

    int wid = word_x[bs];
    const float* wrow = word_emb + (size_t)wid*100;
    float* xo = g_x + (size_t)bs*130;
    for (int i = lane; i < 100; i += 32) xo[i] = wrow[i];
    if (lane < 30) xo[100 + lane] = best + conv_b[lane];
}

// ---------------- kernel 1b: pretranspose input weights -> g_wt[k][n] ----------------
__global__ __launch_bounds__(256) void k_wt(
    const float* __restrict__ wih_f, const float* __restrict__ wih_b)
{
    int idx = blockIdx.x*256 + threadIdx.x;       // 130*800 = 104000
    if (idx >= 130*800) return;
    int k = idx / 800, n = idx % 800;
    g_wt[idx] = (n < 400) ? wih_f[(size_t)n*130 + k] : wih_b[(size_t)(n-400)*130 + k];
}

// ---------------- kernel 2: input-projection SGEMM (f32x2) -> g_xw ----------------
// 128x128 tile, 256 threads, micro = 4 row-pairs x 8 cols (32 f32x2 accs).
__global__ __launch_bounds__(256,2) void k_gemm_in(
    const float* __restrict__ bih_f, const float* __restrict__ bhh_f,
    const float* __restrict__ bih_b, const float* __restrict__ bhh_b)
{
    __shared__ float2 As2[64*66];   // [row-pair mp][k]   rows (2mp, 2mp+1)
    __shared__ float  Bs [65*132];  // [k][n-local padded]

    int tid = threadIdx.x;
    int m0 = blockIdx.y*128;
    int n0 = blockIdx.x*128;
    int tx = tid & 15, ty = tid >> 4;

    u64 acc[4][8];
#pragma unroll
    for (int r=0;r<4;r++)
#pragma unroll
        for (int c=0;c<8;c++) acc[r][c] = 0ull;

    for (int k0=0; k0<130; k0+=65){
        for (int idx=tid; idx<64*65; idx+=256){
            int mp = idx/65, k = idx%65;
            float lo = g_x[(size_t)(m0+2*mp  )*130 + k0 + k];
            float hi = g_x[(size_t)(m0+2*mp+1)*130 + k0 + k];
            As2[mp*66 + k] = make_float2(lo, hi);
        }
        for (int idx=tid; idx<65*128; idx+=256){
            int k = idx >> 7, nl = idx & 127;
            int n = n0+nl;
            Bs[k*132 + nl] = (n < 800) ? g_wt[(size_t)(k0+k)*800 + n] : 0.0f;
        }
        __syncthreads();
#pragma unroll 5
        for (int k=0;k<65;k++){
            u64 a2[4];
#pragma unroll
            for (int r=0;r<4;r++)
                a2[r] = *(const u64*)&As2[(ty*4+r)*66 + k];
            float4 bA = *(const float4*)&Bs[k*132 + tx*8];
            float4 bB = *(const float4*)&Bs[k*132 + tx*8 + 4];
            u64 b[8];
            b[0]=pack2(bA.x,bA.x); b[1]=pack2(bA.y,bA.y);
            b[2]=pack2(bA.z,bA.z); b[3]=pack2(bA.w,bA.w);
            b[4]=pack2(bB.x,bB.x); b[5]=pack2(bB.y,bB.y);
            b[6]=pack2(bB.z,bB.z); b[7]=pack2(bB.w,bB.w);
#pragma unroll
            for (int r=0;r<4;r++)
#pragma unroll
                for (int c=0;c<8;c++)
                    fma2(acc[r][c], a2[r], b[c]);
        }
        __syncthreads();
    }

#pragma unroll
    for (int r=0;r<4;r++)
#pragma unroll
        for (int c=0;c<8;c++){
            int n = n0 + tx*8 + c;
            if (n < 800){
                int dir = n/400, jj = n%400;
                float bias = dir ? (bih_b[jj]+bhh_b[jj]) : (bih_f[jj]+bhh_f[jj]);
                float2 v = unpack2(acc[r][c]);
                int m = m0 + ty*8 + 2*r;
                float* dst = g_xw + (size_t)dir*GM*400 + (size_t)m*400 + jj;
                dst[0]   = v.x + bias;
                dst[400] = v.y + bias;
            }
        }
}

// ---------------- kernel 3: LSTM recurrence, K-split + xw prefetch -> g_h ----------------
__global__ __launch_bounds__(800,1) void k_lstm(
    const float* __restrict__ whh_f, const float* __restrict__ whh_b)
{
    int bx  = blockIdx.x;
    int dir = bx >> 6;
    int pr  = bx & 63;
    int b0  = pr*2, b1 = b0+1;
    int tid = threadIdx.x;
    int half = (tid >= 400);
    int j    = half ? tid - 400 : tid;   // gate row 0..399
    int q0   = half ? 13 : 0;            // float4-group offset into h
    int nq   = half ? 12 : 13;

    const float* whh = dir ? whh_b : whh_f;
    const ulonglong2* wrow = (const ulonglong2*)(whh + (size_t)j*100);
    ulonglong2 w[13];
#pragma unroll
    for (int q=0;q<13;q++){
        if (q < nq) w[q] = wrow[q0+q];
        else { w[q].x = 0ull; w[q].y = 0ull; }
    }

    __shared__ float h_s[2][112];     // zero-padded; group 25 reads land in zeros
    __shared__ float sp[2][2][400];   // [half][batch][gate]
    if (tid < 224) ((float*)h_s)[tid] = 0.0f;
    float c_reg = 0.0f;

    const float* xw   = g_xw + (size_t)dir*GM*400;
    float*       hout = g_h  + (size_t)dir*GM*100;
    __syncthreads();

    // prefetch step 0's xw
    int t0 = dir ? 255 : 0;
    float a0 = 0.0f, a1 = 0.0f;
    if (!half){
        a0 = xw[(size_t)(b0*256+t0)*400 + j];
        a1 = xw[(size_t)(b1*256+t0)*400 + j];
    }

    for (int step=0; step<256; step++){
        int t = dir ? (255-step) : step;

        // prefetch next step's xw (consumed after 2 barriers -> fully hidden)
        float na0 = 0.0f, na1 = 0.0f;
        if (!half && step < 255){
            int tn = dir ? (254-step) : (step+1);
            na0 = xw[(size_t)(b0*256+tn)*400 + j];
            na1 = xw[(size_t)(b1*256+tn)*400 + j];
        }

        u64 s0=0ull, s0b=0ull, s1=0ull, s1b=0ull;
#pragma unroll
        for (int q=0;q<13;q++){
            ulonglong2 wq = w[q];
            ulonglong2 h0 = *(const ulonglong2*)&h_s[0][(q0+q)*4];
            ulonglong2 h1 = *(const ulonglong2*)&h_s[1][(q0+q)*4];
            fma2(s0,  wq.x, h0.x);
            fma2(s0b, wq.y, h0.y);
            fma2(s1,  wq.x, h1.x);
            fma2(s1b, wq.y, h1.y);
        }
        float2 u0 = unpack2(s0), u0b = unpack2(s0b);
        float2 u1 = unpack2(s1), u1b = unpack2(s1b);
        sp[half][0][j] = a0 + ((u0.x+u0.y)+(u0b.x+u0b.y));
        sp[half][1][j] = a1 + ((u1.x+u1.y)+(u1b.x+u1b.y));
        __syncthreads();

        if (tid < 200){
            int bb = (tid >= 100), k = tid - bb*100;
            float gi = sp[0][bb][k]     + sp[1][bb][k];
            float gf = sp[0][bb][100+k] + sp[1][bb][100+k];
            float gg = sp[0][bb][200+k] + sp[1][bb][200+k];
            float go = sp[0][bb][300+k] + sp[1][bb][300+k];
            float ct = msigm(gf)*c_reg + msigm(gi)*mtanh(gg);
            c_reg = ct;
            float h = msigm(go)*mtanh(ct);
            h_s[bb][k] = h;
            hout[(size_t)((bb?b1:b0)*256+t)*100 + k] = h;
        }
        __syncthreads();
        a0 = na0; a1 = na1;
    }
}

// ---------------- kernel 4: emission projection (tiled) -> g_em ----------------
__global__ __launch_bounds__(256) void k_emis(
    const float* __restrict__ proj_w, const float* __restrict__ proj_b)
{
    __shared__ float hs[64*204];   // [m][k] padded row stride
    __shared__ float pw[200*32];   // [k][tag]
    __shared__ float pb[32];

    int tid = threadIdx.x;
    int bs0 = blockIdx.x*64;

    for (int idx=tid; idx<6400; idx+=256){
        int tag = idx/200, k = idx%200;
        pw[k*32+tag] = proj_w[idx];
    }
    if (tid < 32) pb[tid] = proj_b[tid];

    for (int idx=tid; idx<64*50; idx+=256){
        int m = idx/50, q = idx%50;
        int bs = bs0 + m;
        const float* src = (q < 25) ? (g_h + (size_t)bs*100 + q*4)
                                    : (g_h + (size_t)GM*100 + (size_t)bs*100 + (q-25)*4);
        float4 v = *(const float4*)src;
        *(float4*)&hs[m*204 + q*4] = v;
    }
    __syncthreads();

    int tag  = tid & 31;
    int msub = tid >> 5;           // 0..7

    float acc[8];
#pragma unroll
    for (int i=0;i<8;i++) acc[i] = pb[tag];

    for (int k=0;k<200;k++){
        float pwv = pw[k*32 + tag];
#pragma unroll
        for (int i=0;i<8;i++)
            acc[i] += hs[(msub + 8*i)*204 + k] * pwv;   // broadcast read
    }
#pragma unroll
    for (int i=0;i<8;i++)
        g_em[(size_t)(bs0 + msub + 8*i)*32 + tag] = acc[i];
}

// ---------------- kernel 5: CRF (exp-factorized, lane0-normalized) ----------------
// Step 0 in closed form (only active source is START). Then per step:
// m = la[lane0] broadcast (1 shfl); s = sum_i e^{la_i-m} T_ij. Spread of la
// across tags is bounded (~20), so e^{la-m} cannot overflow; underflow -> 0 is exact.
__global__ __launch_bounds__(32) void k_crf(
    const float* __restrict__ trans, const int* __restrict__ y, float* __restrict__ out)
{
    __shared__ float E_s[32];
    int j = threadIdx.x, b = blockIdx.x;

    float T[32];
#pragma unroll
    for (int i=0;i<32;i++) T[i] = __expf(trans[i*32 + j]);   // exp(NEG)=0, safe
    float tend = trans[j*32 + 31];                           // trans[j, END]

    float score = 0.0f;
    for (int t=j; t<256; t+=32){
        int cur  = y[b*256+t];
        int prev = (t==0) ? 30 : y[b*256+t-1];
        score += g_em[(size_t)(b*256+t)*32 + cur] + trans[prev*32+cur];
    }
    __syncwarp();

    // step 0 closed form: la_1[j] = em_0[j] + trans[START][j]
    float la  = g_em[(size_t)(b*256)*32 + j] + trans[30*32 + j];
    float emv = g_em[(size_t)(b*256+1)*32 + j];

    for (int t=1; t<256; t++){
        float em_next = (t < 255) ? g_em[(size_t)(b*256+t+1)*32 + j] : 0.0f;

        float m = __shfl_sync(0xffffffffu, la, 0);
        E_s[j] = __expf(la - m);
        __syncwarp();
        float s = 0.0f;
#pragma unroll
        for (int i=0;i<32;i++) s += E_s[i]*T[i];
        la = emv + m + __logf(s);
        __syncwarp();
        emv = em_next;
    }

    la += tend;
    float m = la;
#pragma unroll
    for (int o=16;o>0;o>>=1) m = fmaxf(m, __shfl_xor_sync(0xffffffffu, m, o));
    float e = __expf(la - m);
#pragma unroll
    for (int o=16;o>0;o>>=1) e += __shfl_xor_sync(0xffffffffu, e, o);
    float total = m + __logf(e);

#pragma unroll
    for (int o=16;o>0;o>>=1) score += __shfl_xor_sync(0xffffffffu, score, o);

    if (j==0){
        score += trans[y[b*256+255]*32 + 31];
        atomicAdd(out, (total - score) * (1.0f/128.0f));
    }
}

// ---------------- launch ----------------
extern "C" void kernel_launch(void* const* d_in, const int* in_sizes, int n_in,
                              void* d_out, int out_size)
{
    const float* word_emb = (const float*)d_in[0];
    const float* char_emb = (const float*)d_in[1];
    const float* conv_w   = (const float*)d_in[2];
    const float* conv_b   = (const float*)d_in[3];
    const float* wih_f    = (const float*)d_in[4];
    const float* whh_f    = (const float*)d_in[5];
    const float* bih_f    = (const float*)d_in[6];
    const float* bhh_f    = (const float*)d_in[7];
    const float* wih_b    = (const float*)d_in[8];
    const float* whh_b    = (const float*)d_in[9];
    const float* bih_b    = (const float*)d_in[10];
    const float* bhh_b    = (const float*)d_in[11];
    const float* proj_w   = (const float*)d_in[12];
    const float* proj_b   = (const float*)d_in[13];
    const float* trans    = (const float*)d_in[14];
    const int*   word_x   = (const int*)d_in[15];
    const int*   char_x   = (const int*)d_in[16];
    const int*   y        = (const int*)d_in[17];
    float* out = (float*)d_out;

    k_wt<<<(130*800+255)/256,256>>>(wih_f, wih_b);
    k_embed_cnn<<<8192,128>>>(word_emb, char_emb, conv_w, conv_b, word_x, char_x);
    dim3 gg(7, 256);
    k_gemm_in<<<gg,256>>>(bih_f, bhh_f, bih_b, bhh_b);
    k_lstm<<<128,800>>>(whh_f, whh_b);
    k_emis<<<512,256>>>(proj_w, proj_b);
    cudaMemsetAsync(out, 0, sizeof(float));
    k_crf<<<128,32>>>(trans, y, out);
}

// round 7
// speedup vs baseline: 1.8140x; 1.1468x over previous
#include <cuda_runtime.h>
#include <cstdint>
#include <cstddef>

#define Bn   128
#define Sn   256
#define GM   (Bn*Sn)         // 32768
#define NEGV (-10000.0f)

typedef unsigned long long u64;

// ---------------- scratch (device globals; no allocation allowed) ----------------
__device__ float g_x [GM*130];            // concat(word_emb, char_feat)
__device__ float g_wt[130*800];           // transposed input weights [k][n]
__device__ float g_xw[2u*GM*400];         // x @ wih^T + (bih+bhh), per direction
__device__ float g_h [2u*GM*100];         // hidden states f/b
__device__ float g_em[GM*32];             // emissions
__device__ float g_P [100*96];            // char-conv table [c][k*32+f]

__device__ __forceinline__ float mtanh(float x){
    float r; asm("tanh.approx.f32 %0, %1;" : "=f"(r) : "f"(x)); return r;
}
__device__ __forceinline__ float msigm(float x){ return fmaf(mtanh(0.5f*x), 0.5f, 0.5f); }

// packed f32x2 helpers (Blackwell; ptxas never auto-fuses these)
__device__ __forceinline__ void fma2(u64 &d, u64 a, u64 b){
    asm("fma.rn.f32x2 %0, %1, %2, %0;" : "+l"(d) : "l"(a), "l"(b));
}
__device__ __forceinline__ u64 pack2(float x, float y){
    u64 r; asm("mov.b64 %0, {%1, %2};" : "=l"(r) : "f"(x), "f"(y)); return r;
}
__device__ __forceinline__ float2 unpack2(u64 v){
    float2 r; asm("mov.b64 {%0, %1}, %2;" : "=f"(r.x), "=f"(r.y) : "l"(v)); return r;
}

// ---------------- kernel 0: char-conv table  P[c][k*32+f] ----------------
__global__ __launch_bounds__(256) void k_ptab(
    const float* __restrict__ conv_w, const float* __restrict__ char_emb)
{
    int idx = blockIdx.x*256 + threadIdx.x;     // 100*96 = 9600
    if (idx >= 9600) return;
    int c = idx / 96, r = idx % 96, k = r >> 5, f = r & 31;
    float s = 0.0f;
    if (f < 30){
        const float* w = conv_w + f*90 + k*30;
        const float* e = char_emb + c*30;
#pragma unroll
        for (int d=0; d<30; d++) s += w[d]*e[d];
    }
    g_P[idx] = s;
}

// ---------------- kernel 1: embedding concat + table-lookup char CNN -> g_x ----------------
// conv output at p = P[c_{p-2}][0][f] + P[c_{p-1}][1][f] + P[c_p][2][f] (valid l only).
// Warp per token (lane = filter); 8 tokens per warp, 64 per block.
__global__ __launch_bounds__(256) void k_cnn(
    const float* __restrict__ word_emb, const float* __restrict__ conv_b,
    const int*   __restrict__ word_x,   const int*   __restrict__ char_x)
{
    __shared__ float sP[9600];
    __shared__ float sb[32];

    int tid  = threadIdx.x;
    int lane = tid & 31;
    int wrp  = tid >> 5;

    for (int i = tid; i < 9600; i += 256) sP[i] = g_P[i];
    if (tid < 30) sb[tid] = conv_b[tid];
    __syncthreads();

    int base = blockIdx.x*64 + wrp*8;
#pragma unroll
    for (int i=0;i<8;i++){
        int bs = base + i;

        int cv = 0;
        if (lane < 10) cv = char_x[bs*10 + lane];

        int wid = word_x[bs];
        const float* wrow = word_emb + (size_t)wid*100;
        float* xo = g_x + (size_t)bs*130;
        for (int t = lane; t < 100; t += 32) xo[t] = wrow[t];

        int ci[10];
#pragma unroll
        for (int l=0;l<10;l++)
            ci[l] = __shfl_sync(0xffffffffu, cv, l)*96 + lane;

        float best = -1e30f;
#pragma unroll
        for (int p=0;p<12;p++){
            float acc = 0.0f;
            if (p >= 2)           acc += sP[ci[p-2] +  0];
            if (p >= 1 && p <=10) acc += sP[ci[p-1] + 32];
            if (p <= 9)           acc += sP[ci[p]   + 64];
            best = fmaxf(best, acc);
        }
        if (lane < 30) xo[100 + lane] = best + sb[lane];
    }
}

// ---------------- kernel 1b: pretranspose input weights -> g_wt[k][n] ----------------
__global__ __launch_bounds__(256) void k_wt(
    const float* __restrict__ wih_f, const float* __restrict__ wih_b)
{
    int idx = blockIdx.x*256 + threadIdx.x;       // 130*800 = 104000
    if (idx >= 130*800) return;
    int k = idx / 800, n = idx % 800;
    g_wt[idx] = (n < 400) ? wih_f[(size_t)n*130 + k] : wih_b[(size_t)(n-400)*130 + k];
}

// ---------------- kernel 2: input-projection SGEMM (f32x2) -> g_xw ----------------
__global__ __launch_bounds__(256,2) void k_gemm_in(
    const float* __restrict__ bih_f, const float* __restrict__ bhh_f,
    const float* __restrict__ bih_b, const float* __restrict__ bhh_b)
{
    __shared__ float2 As2[64*66];   // [row-pair mp][k]   rows (2mp, 2mp+1)
    __shared__ float  Bs [65*132];  // [k][n-local padded]

    int tid = threadIdx.x;
    int m0 = blockIdx.y*128;
    int n0 = blockIdx.x*128;
    int tx = tid & 15, ty = tid >> 4;

    u64 acc[4][8];
#pragma unroll
    for (int r=0;r<4;r++)
#pragma unroll
        for (int c=0;c<8;c++) acc[r][c] = 0ull;

    for (int k0=0; k0<130; k0+=65){
        for (int idx=tid; idx<64*65; idx+=256){
            int mp = idx/65, k = idx%65;
            float lo = g_x[(size_t)(m0+2*mp  )*130 + k0 + k];
            float hi = g_x[(size_t)(m0+2*mp+1)*130 + k0 + k];
            As2[mp*66 + k] = make_float2(lo, hi);
        }
        for (int idx=tid; idx<65*128; idx+=256){
            int k = idx >> 7, nl = idx & 127;
            int n = n0+nl;
            Bs[k*132 + nl] = (n < 800) ? g_wt[(size_t)(k0+k)*800 + n] : 0.0f;
        }
        __syncthreads();
#pragma unroll 5
        for (int k=0;k<65;k++){
            u64 a2[4];
#pragma unroll
            for (int r=0;r<4;r++)
                a2[r] = *(const u64*)&As2[(ty*4+r)*66 + k];
            float4 bA = *(const float4*)&Bs[k*132 + tx*8];
            float4 bB = *(const float4*)&Bs[k*132 + tx*8 + 4];
            u64 b[8];
            b[0]=pack2(bA.x,bA.x); b[1]=pack2(bA.y,bA.y);
            b[2]=pack2(bA.z,bA.z); b[3]=pack2(bA.w,bA.w);
            b[4]=pack2(bB.x,bB.x); b[5]=pack2(bB.y,bB.y);
            b[6]=pack2(bB.z,bB.z); b[7]=pack2(bB.w,bB.w);
#pragma unroll
            for (int r=0;r<4;r++)
#pragma unroll
                for (int c=0;c<8;c++)
                    fma2(acc[r][c], a2[r], b[c]);
        }
        __syncthreads();
    }

#pragma unroll
    for (int r=0;r<4;r++)
#pragma unroll
        for (int c=0;c<8;c++){
            int n = n0 + tx*8 + c;
            if (n < 800){
                int dir = n/400, jj = n%400;
                float bias = dir ? (bih_b[jj]+bhh_b[jj]) : (bih_f[jj]+bhh_f[jj]);
                float2 v = unpack2(acc[r][c]);
                int m = m0 + ty*8 + 2*r;
                float* dst = g_xw + (size_t)dir*GM*400 + (size_t)m*400 + jj;
                dst[0]   = v.x + bias;
                dst[400] = v.y + bias;
            }
        }
}

// ---------------- kernel 3: LSTM recurrence, K-split + xw prefetch -> g_h ----------------
// half0 prefetches batch0's xw, half1 batch1's (balanced LDG).
__global__ __launch_bounds__(800,1) void k_lstm(
    const float* __restrict__ whh_f, const float* __restrict__ whh_b)
{
    int bx  = blockIdx.x;
    int dir = bx >> 6;
    int pr  = bx & 63;
    int b0  = pr*2, b1 = b0+1;
    int tid = threadIdx.x;
    int half = (tid >= 400);
    int j    = half ? tid - 400 : tid;   // gate row 0..399
    int q0   = half ? 13 : 0;            // float4-group offset into h
    int nq   = half ? 12 : 13;
    int bmine = half ? b1 : b0;

    const float* whh = dir ? whh_b : whh_f;
    const ulonglong2* wrow = (const ulonglong2*)(whh + (size_t)j*100);
    ulonglong2 w[13];
#pragma unroll
    for (int q=0;q<13;q++){
        if (q < nq) w[q] = wrow[q0+q];
        else { w[q].x = 0ull; w[q].y = 0ull; }
    }

    __shared__ float h_s[2][112];     // zero-padded; group 25 reads land in zeros
    __shared__ float sp[2][2][400];   // [half][batch][gate]
    if (tid < 224) ((float*)h_s)[tid] = 0.0f;
    float c_reg = 0.0f;

    const float* xw   = g_xw + (size_t)dir*GM*400;
    float*       hout = g_h  + (size_t)dir*GM*100;
    __syncthreads();

    // prefetch step 0's xw (each half loads its own batch's value)
    int t0 = dir ? 255 : 0;
    float av = xw[(size_t)(bmine*256+t0)*400 + j];

    for (int step=0; step<256; step++){
        int t = dir ? (255-step) : step;

        float nav = 0.0f;
        if (step < 255){
            int tn = dir ? (254-step) : (step+1);
            nav = xw[(size_t)(bmine*256+tn)*400 + j];
        }

        u64 s0=0ull, s0b=0ull, s1=0ull, s1b=0ull;
#pragma unroll
        for (int q=0;q<13;q++){
            ulonglong2 wq = w[q];
            ulonglong2 h0 = *(const ulonglong2*)&h_s[0][(q0+q)*4];
            ulonglong2 h1 = *(const ulonglong2*)&h_s[1][(q0+q)*4];
            fma2(s0,  wq.x, h0.x);
            fma2(s0b, wq.y, h0.y);
            fma2(s1,  wq.x, h1.x);
            fma2(s1b, wq.y, h1.y);
        }
        float2 u0 = unpack2(s0), u0b = unpack2(s0b);
        float2 u1 = unpack2(s1), u1b = unpack2(s1b);
        float d0 = (u0.x+u0.y)+(u0b.x+u0b.y);
        float d1 = (u1.x+u1.y)+(u1b.x+u1b.y);
        sp[half][0][j] = half ? d0 : d0 + av;
        sp[half][1][j] = half ? d1 + av : d1;
        __syncthreads();

        if (tid < 200){
            int bb = (tid >= 100), k = tid - bb*100;
            float gi = sp[0][bb][k]     + sp[1][bb][k];
            float gf = sp[0][bb][100+k] + sp[1][bb][100+k];
            float gg = sp[0][bb][200+k] + sp[1][bb][200+k];
            float go = sp[0][bb][300+k] + sp[1][bb][300+k];
            float ct = msigm(gf)*c_reg + msigm(gi)*mtanh(gg);
            c_reg = ct;
            float h = msigm(go)*mtanh(ct);
            h_s[bb][k] = h;
            hout[(size_t)((bb?b1:b0)*256+t)*100 + k] = h;
        }
        __syncthreads();
        av = nav;
    }
}

// ---------------- kernel 4: emission projection (tiled) -> g_em ----------------
__global__ __launch_bounds__(256) void k_emis(
    const float* __restrict__ proj_w, const float* __restrict__ proj_b)
{
    __shared__ float hs[64*204];   // [m][k] padded row stride
    __shared__ float pw[200*32];   // [k][tag]
    __shared__ float pb[32];

    int tid = threadIdx.x;
    int bs0 = blockIdx.x*64;

    for (int idx=tid; idx<6400; idx+=256){
        int tag = idx/200, k = idx%200;
        pw[k*32+tag] = proj_w[idx];
    }
    if (tid < 32) pb[tid] = proj_b[tid];

    for (int idx=tid; idx<64*50; idx+=256){
        int m = idx/50, q = idx%50;
        int bs = bs0 + m;
        const float* src = (q < 25) ? (g_h + (size_t)bs*100 + q*4)
                                    : (g_h + (size_t)GM*100 + (size_t)bs*100 + (q-25)*4);
        float4 v = *(const float4*)src;
        *(float4*)&hs[m*204 + q*4] = v;
    }
    __syncthreads();

    int tag  = tid & 31;
    int msub = tid >> 5;           // 0..7

    float acc[8];
#pragma unroll
    for (int i=0;i<8;i++) acc[i] = pb[tag];

    for (int k=0;k<200;k++){
        float pwv = pw[k*32 + tag];
#pragma unroll
        for (int i=0;i<8;i++)
            acc[i] += hs[(msub + 8*i)*204 + k] * pwv;   // broadcast read
    }
#pragma unroll
    for (int i=0;i<8;i++)
        g_em[(size_t)(bs0 + msub + 8*i)*32 + tag] = acc[i];
}

// ---------------- kernel 5: CRF (exp-factorized, lane0-normalized, split sums) ----------------
__global__ __launch_bounds__(32) void k_crf(
    const float* __restrict__ trans, const int* __restrict__ y, float* __restrict__ out)
{
    __shared__ float E_s[32];
    int j = threadIdx.x, b = blockIdx.x;

    float T[32];
#pragma unroll
    for (int i=0;i<32;i++) T[i] = __expf(trans[i*32 + j]);   // exp(NEG)=0, safe
    float tend = trans[j*32 + 31];                           // trans[j, END]

    float score = 0.0f;
    for (int t=j; t<256; t+=32){
        int cur  = y[b*256+t];
        int prev = (t==0) ? 30 : y[b*256+t-1];
        score += g_em[(size_t)(b*256+t)*32 + cur] + trans[prev*32+cur];
    }
    __syncwarp();

    // step 0 closed form: la_1[j] = em_0[j] + trans[START][j]
    float la  = g_em[(size_t)(b*256)*32 + j] + trans[30*32 + j];
    float emv = g_em[(size_t)(b*256+1)*32 + j];

    for (int t=1; t<256; t++){
        float em_next = (t < 255) ? g_em[(size_t)(b*256+t+1)*32 + j] : 0.0f;

        float m = __shfl_sync(0xffffffffu, la, 0);
        E_s[j] = __expf(la - m);
        __syncwarp();
        float s0=0.f, s1=0.f, s2=0.f, s3=0.f;
#pragma unroll
        for (int i=0;i<8;i++){
            s0 += E_s[i   ]*T[i   ];
            s1 += E_s[i+ 8]*T[i+ 8];
            s2 += E_s[i+16]*T[i+16];
            s3 += E_s[i+24]*T[i+24];
        }
        la = emv + m + __logf((s0+s1)+(s2+s3));
        __syncwarp();
        emv = em_next;
    }

    la += tend;
    float m = la;
#pragma unroll
    for (int o=16;o>0;o>>=1) m = fmaxf(m, __shfl_xor_sync(0xffffffffu, m, o));
    float e = __expf(la - m);
#pragma unroll
    for (int o=16;o>0;o>>=1) e += __shfl_xor_sync(0xffffffffu, e, o);
    float total = m + __logf(e);

#pragma unroll
    for (int o=16;o>0;o>>=1) score += __shfl_xor_sync(0xffffffffu, score, o);

    if (j==0){
        score += trans[y[b*256+255]*32 + 31];
        atomicAdd(out, (total - score) * (1.0f/128.0f));
    }
}

// ---------------- launch ----------------
extern "C" void kernel_launch(void* const* d_in, const int* in_sizes, int n_in,
                              void* d_out, int out_size)
{
    const float* word_emb = (const float*)d_in[0];
    const float* char_emb = (const float*)d_in[1];
    const float* conv_w   = (const float*)d_in[2];
    const float* conv_b   = (const float*)d_in[3];
    const float* wih_f    = (const float*)d_in[4];
    const float* whh_f    = (const float*)d_in[5];
    const float* bih_f    = (const float*)d_in[6];
    const float* bhh_f    = (const float*)d_in[7];
    const float* wih_b    = (const float*)d_in[8];
    const float* whh_b    = (const float*)d_in[9];
    const float* bih_b    = (const float*)d_in[10];
    const float* bhh_b    = (const float*)d_in[11];
    const float* proj_w   = (const float*)d_in[12];
    const float* proj_b   = (const float*)d_in[13];
    const float* trans    = (const float*)d_in[14];
    const int*   word_x   = (const int*)d_in[15];
    const int*   char_x   = (const int*)d_in[16];
    const int*   y        = (const int*)d_in[17];
    float* out = (float*)d_out;

    k_ptab<<<38,256>>>(conv_w, char_emb);
    k_wt<<<(130*800+255)/256,256>>>(wih_f, wih_b);
    k_cnn<<<512,256>>>(word_emb, conv_b, word_x, char_x);
    dim3 gg(7, 256);
    k_gemm_in<<<gg,256>>>(bih_f, bhh_f, bih_b, bhh_b);
    k_lstm<<<128,800>>>(whh_f, whh_b);
    k_emis<<<512,256>>>(proj_w, proj_b);
    cudaMemsetAsync(out, 0, sizeof(float));
    k_crf<<<128,32>>>(trans, y, out);
}